// round 5
// baseline (speedup 1.0000x reference)
#include <cuda_runtime.h>
#include <cstdint>

// ---------------------------------------------------------------------------
// Problem dims
// ---------------------------------------------------------------------------
#define T_STEPS 1024
#define BATCH   256
#define FDIM    512
#define MROWS   (T_STEPS * BATCH)      // 262144
#define BF      (BATCH * FDIM)         // 131072

// ---------------------------------------------------------------------------
// GEMM tiling: CTA 128m x 64n, 8 warps (2m x 4n), warp tile 64m x 16n.
// K chunks of 128, 3-stage cp.async pipeline. 3 int8 digit planes (radix 256).
// ---------------------------------------------------------------------------
#define CTA_M   128
#define CTA_N   64
#define KC      128
#define NCHUNK  (FDIM / KC)            // 4
#define NSTAGE  3
#define STRIDE  144                    // smem row stride: 128 B data + 16 pad
#define A_BYTES (CTA_M * STRIDE)       // 18432
#define B_BYTES (3 * CTA_N * STRIDE)   // 27648
#define STG_BYTES (A_BYTES + B_BYTES)  // 46080
#define SMEM_TOTAL (NSTAGE * STG_BYTES)// 138240

// Device scratch (static arrays are the sanctioned scratch mechanism)
__device__ int8_t  g_Wq[3 * FDIM * FDIM];          // digit planes d1,d2,d3
__device__ uint8_t g_S8[(size_t)MROWS * FDIM];     // spikes as int8 (134 MB)
__device__ float   g_xs[(size_t)MROWS * FDIM];     // fc outputs (512 MB)

// ---------------------------------------------------------------------------
__device__ __forceinline__ uint32_t smem_u32(const void* p) {
    uint32_t a;
    asm("{ .reg .u64 t; cvta.to.shared.u64 t, %1; cvt.u32.u64 %0, t; }"
        : "=r"(a) : "l"(p));
    return a;
}
__device__ __forceinline__ void cp16(uint32_t dst, const void* src) {
    asm volatile("cp.async.cg.shared.global [%0], [%1], 16;"
                 :: "r"(dst), "l"(src) : "memory");
}
#define LDS32(x, addr) \
    asm volatile("ld.shared.b32 %0, [%1];" : "=r"(x) : "r"(addr))

#define IMMA(c, a, b0_, b1_)                                               \
    asm volatile("mma.sync.aligned.m16n8k32.row.col.s32.s8.s8.s32 "        \
                 "{%0,%1,%2,%3}, {%4,%5,%6,%7}, {%8,%9}, {%0,%1,%2,%3};"   \
                 : "+r"((c)[0]), "+r"((c)[1]), "+r"((c)[2]), "+r"((c)[3])  \
                 : "r"((a)[0]), "r"((a)[1]), "r"((a)[2]), "r"((a)[3]),     \
                   "r"(b0_), "r"(b1_))

// ---------------------------------------------------------------------------
// Kernel 1: W -> 3 balanced radix-256 int8 digit planes.
// Q = rn(w * 2^25) (exact mult); w == (d1*2^16 + d2*2^8 + d3) * 2^-25 + r,
// |r| <= 2^-26. Digits fit int8 for |w| <= 0.249 (gaussian max ~0.225).
// ---------------------------------------------------------------------------
__global__ void wsplit_kernel(const float* __restrict__ W) {
    int idx = blockIdx.x * 256 + threadIdx.x;       // 262144 = 512*512
    float w = W[idx];
    int Q  = __float2int_rn(w * 33554432.0f);       // 2^25
    int d3 = ((Q + 128) & 255) - 128;
    int Q2 = (Q - d3) >> 8;
    int d2 = ((Q2 + 128) & 255) - 128;
    int d1 = (Q2 - d2) >> 8;
    g_Wq[idx]                 = (int8_t)d1;
    g_Wq[FDIM * FDIM + idx]   = (int8_t)d2;
    g_Wq[2 * FDIM * FDIM + idx] = (int8_t)d3;
}

// ---------------------------------------------------------------------------
// Kernel 2: spikes fp32 (exactly 0/1) -> uint8
// ---------------------------------------------------------------------------
__global__ void cvt8_kernel(const float* __restrict__ s) {
    size_t k = (size_t)blockIdx.x * 256 + threadIdx.x;   // 16 elems per thread
    const float4* p = (const float4*)s + k * 4;
    uint32_t w[4];
    #pragma unroll
    for (int j = 0; j < 4; j++) {
        float4 v = p[j];
        w[j] = (v.x != 0.0f ? 1u : 0u)
             | (v.y != 0.0f ? 1u : 0u) << 8
             | (v.z != 0.0f ? 1u : 0u) << 16
             | (v.w != 0.0f ? 1u : 0u) << 24;
    }
    ((uint4*)g_S8)[k] = make_uint4(w[0], w[1], w[2], w[3]);
}

// ---------------------------------------------------------------------------
// Kernel 3: int8 GEMM via mma.sync.m16n8k32.
// xs[m][n] = ( acc_d1*2^16 + acc_d2*2^8 + acc_d3 ) * 2^-25, exact int32 accum.
// ---------------------------------------------------------------------------
__global__ void __launch_bounds__(256)
gemm_kernel() {
    extern __shared__ char smem[];
    const uint32_t sb = smem_u32(smem);
    const int tid  = threadIdx.x;
    const int lane = tid & 31, wid = tid >> 5;
    const int wm = wid & 1, wn = wid >> 1;       // 2 m-halves x 4 n-quarters
    const int n0 = blockIdx.x * CTA_N;
    const size_t m0 = (size_t)blockIdx.y * CTA_M;

    int ac[3][4][2][4];
    #pragma unroll
    for (int s = 0; s < 3; s++)
        #pragma unroll
        for (int mt = 0; mt < 4; mt++)
            #pragma unroll
            for (int nt = 0; nt < 2; nt++)
                #pragma unroll
                for (int j = 0; j < 4; j++) ac[s][mt][nt][j] = 0;

    // ---- stage loader: A[128m x 128k] s8 + 3 x B[64n x 128k] s8 ----
    auto stage_load = [&](int c, int stg) {
        const uint32_t base = sb + stg * STG_BYTES;
        #pragma unroll
        for (int q = 0; q < 4; q++) {            // A: 1024 cp16
            int u = q * 256 + tid;
            int row = u >> 3, seg = u & 7;
            cp16(base + row * STRIDE + seg * 16,
                 g_S8 + (m0 + row) * FDIM + c * KC + seg * 16);
        }
        #pragma unroll
        for (int q = 0; q < 6; q++) {            // B: 1536 cp16
            int u = q * 256 + tid;
            int split = u >> 9, rem = u & 511;
            int row = rem >> 3, seg = rem & 7;
            cp16(base + A_BYTES + split * (CTA_N * STRIDE) + row * STRIDE + seg * 16,
                 g_Wq + (size_t)split * (FDIM * FDIM)
                      + (size_t)(n0 + row) * FDIM + c * KC + seg * 16);
        }
        asm volatile("cp.async.commit_group;" ::: "memory");
    };

    stage_load(0, 0);
    stage_load(1, 1);
    stage_load(2, 2);

    #pragma unroll
    for (int c = 0; c < NCHUNK; c++) {
        if (c <= 1)      asm volatile("cp.async.wait_group 2;" ::: "memory");
        else if (c == 2) asm volatile("cp.async.wait_group 1;" ::: "memory");
        else             asm volatile("cp.async.wait_group 0;" ::: "memory");
        __syncthreads();

        const int stg = c % NSTAGE;
        // fragment base addresses (quad pattern; stride 144 B is conflict-free)
        const uint32_t abase = sb + stg * STG_BYTES
            + (uint32_t)((wm * 64 + (lane >> 2)) * STRIDE + (lane & 3) * 4);
        const uint32_t bbase = sb + stg * STG_BYTES + A_BYTES
            + (uint32_t)((wn * 16 + (lane >> 2)) * STRIDE + (lane & 3) * 4);

        #pragma unroll
        for (int ks = 0; ks < 4; ks++) {         // 4 k32 steps per chunk
            uint32_t a[4][4];
            #pragma unroll
            for (int mt = 0; mt < 4; mt++) {
                uint32_t ad = abase + mt * 16 * STRIDE + ks * 32;
                LDS32(a[mt][0], ad);
                LDS32(a[mt][1], ad + 8 * STRIDE);
                LDS32(a[mt][2], ad + 16);
                LDS32(a[mt][3], ad + 8 * STRIDE + 16);
            }
            #pragma unroll
            for (int sp = 0; sp < 3; sp++)
                #pragma unroll
                for (int nt = 0; nt < 2; nt++) {
                    uint32_t bd = bbase + sp * (CTA_N * STRIDE)
                                + nt * 8 * STRIDE + ks * 32;
                    uint32_t b0, b1;
                    LDS32(b0, bd);
                    LDS32(b1, bd + 16);
                    #pragma unroll
                    for (int mt = 0; mt < 4; mt++)
                        IMMA(ac[sp][mt][nt], a[mt], b0, b1);
                }
        }
        __syncthreads();
        if (c + NSTAGE < NCHUNK) stage_load(c + NSTAGE, (c + NSTAGE) % NSTAGE);
    }

    // ---- epilogue: exact digit recombination, 1 rounding per element ----
    #pragma unroll
    for (int mt = 0; mt < 4; mt++)
        #pragma unroll
        for (int nt = 0; nt < 2; nt++) {
            const size_t row = m0 + wm * 64 + mt * 16 + (lane >> 2);
            const int    col = n0 + wn * 16 + nt * 8 + (lane & 3) * 2;
            float x[4];
            #pragma unroll
            for (int j = 0; j < 4; j++) {
                int hi = ac[0][mt][nt][j];
                int lo = ac[1][mt][nt][j] * 256 + ac[2][mt][nt][j];
                x[j] = __fadd_rn(__int2float_rn(hi) * 0x1p-9f,
                                 __int2float_rn(lo) * 0x1p-25f);
            }
            *(float2*)(g_xs + row * FDIM + col)       = make_float2(x[0], x[1]);
            *(float2*)(g_xs + (row + 8) * FDIM + col) = make_float2(x[2], x[3]);
        }
}

// ---------------------------------------------------------------------------
// Kernel 4: LIF scan. Thread = one neuron (b,f); xs[t][bf] coalesced.
// fp32-exact in reference op order.
// ---------------------------------------------------------------------------
__global__ void __launch_bounds__(256)
scan_kernel(float* __restrict__ out) {
    const int bf = blockIdx.x * 256 + threadIdx.x;
    const float* p = g_xs + bf;
    float v = 0.0f, i = 0.0f, z = 0.0f;

    for (int t = 0; t < T_STEPS; t += 8) {
        float x[8];
        #pragma unroll
        for (int u = 0; u < 8; u++)
            x[u] = p[(size_t)(t + u) * BF];
        #pragma unroll
        for (int u = 0; u < 8; u++) {
            float vd = __fadd_rn(v, __fmul_rn(0.1f, __fadd_rn(-v, i)));
            float id = __fadd_rn(i, -__fmul_rn(0.2f, i));
            bool s = vd > 1.0f;
            z = s ? 1.0f : 0.0f;
            v = s ? 0.0f : vd;
            i = __fadd_rn(id, x[u]);
        }
    }
    out[bf]          = z;
    out[BF + bf]     = v;
    out[2 * BF + bf] = i;
}

// ---------------------------------------------------------------------------
extern "C" void kernel_launch(void* const* d_in, const int* in_sizes, int n_in,
                              void* d_out, int out_size) {
    const float* spikes = (const float*)d_in[0];  // [T, B, F] fp32 (binary)
    const float* W      = (const float*)d_in[1];  // [F, F] fp32
    float* out          = (float*)d_out;          // [3, B, F] fp32
    (void)in_sizes; (void)n_in; (void)out_size;

    cudaFuncSetAttribute(gemm_kernel,
                         cudaFuncAttributeMaxDynamicSharedMemorySize, SMEM_TOTAL);

    wsplit_kernel<<<(FDIM * FDIM) / 256, 256>>>(W);
    cvt8_kernel<<<(int)((size_t)MROWS * FDIM / 16 / 256), 256>>>(spikes);
    gemm_kernel<<<dim3(FDIM / CTA_N, MROWS / CTA_M), 256, SMEM_TOTAL>>>();
    scan_kernel<<<BF / 256, 256>>>(out);
}

// round 7
// speedup vs baseline: 2.8371x; 2.8371x over previous
#include <cuda_runtime.h>
#include <cuda_bf16.h>
#include <cstdint>

// ---------------------------------------------------------------------------
#define T_STEPS 1024
#define BATCH   256
#define FDIM    512
#define MROWS   (T_STEPS * BATCH)      // 262144
#define BF      (BATCH * FDIM)         // 131072

// GEMM tiling: CTA 256m x 128n, KC=64, 2-stage cp.async, 8 warps (4m x 2n),
// warp tile 64m x 64n, 3 bf16 planes accumulated into one fp32 accumulator.
#define MT      256
#define NT      128
#define KC      64
#define NCHUNK  (FDIM / KC)            // 8
#define A_SZ    (MT * 128)             // 32768 B  (256 rows x 128 B)
#define B_SZ    (3 * NT * 128)         // 49152 B  (3 planes x 128 rows x 128 B)
#define STG     (A_SZ + B_SZ)          // 81920 B
#define SMEM_TOTAL (2 * STG)           // 163840 B

// Device scratch (static arrays are the sanctioned scratch mechanism)
__device__ uint16_t g_Sb[(size_t)MROWS * FDIM];        // spikes bf16 (268 MB)
__device__ uint16_t g_Wp[3 * FDIM * FDIM];             // bf16 planes hi/mid/lo
__device__ float    g_xs[(size_t)MROWS * FDIM];        // fc outputs (512 MB)

// ---------------------------------------------------------------------------
__device__ __forceinline__ uint32_t smem_u32(const void* p) {
    uint32_t a;
    asm("{ .reg .u64 t; cvta.to.shared.u64 t, %1; cvt.u32.u64 %0, t; }"
        : "=r"(a) : "l"(p));
    return a;
}
__device__ __forceinline__ void cp16(uint32_t dst, const void* src) {
    asm volatile("cp.async.cg.shared.global [%0], [%1], 16;"
                 :: "r"(dst), "l"(src) : "memory");
}
#define LDSM4(r0, r1, r2, r3, addr)                                        \
    asm volatile("ldmatrix.sync.aligned.m8n8.x4.shared.b16 "               \
                 "{%0,%1,%2,%3}, [%4];"                                    \
                 : "=r"(r0), "=r"(r1), "=r"(r2), "=r"(r3) : "r"(addr))

#define HMMA(c, a, b0_, b1_)                                               \
    asm volatile("mma.sync.aligned.m16n8k16.row.col.f32.bf16.bf16.f32 "    \
                 "{%0,%1,%2,%3}, {%4,%5,%6,%7}, {%8,%9}, {%0,%1,%2,%3};"   \
                 : "+f"((c)[0]), "+f"((c)[1]), "+f"((c)[2]), "+f"((c)[3])  \
                 : "r"((a)[0]), "r"((a)[1]), "r"((a)[2]), "r"((a)[3]),     \
                   "r"(b0_), "r"(b1_))

// ---------------------------------------------------------------------------
// Kernel 1: exact 3-way bf16 split of W. w = bh + bm + bl + r, |r|<=|w|*2^-27.
// ---------------------------------------------------------------------------
__global__ void wsplit_kernel(const float* __restrict__ W) {
    int idx = blockIdx.x * 256 + threadIdx.x;       // 262144 = 512*512
    float w = W[idx];
    __nv_bfloat16 bh = __float2bfloat16_rn(w);
    float r1 = w - __bfloat162float(bh);            // exact
    __nv_bfloat16 bm = __float2bfloat16_rn(r1);
    float r2 = r1 - __bfloat162float(bm);           // exact
    __nv_bfloat16 bl = __float2bfloat16_rn(r2);
    g_Wp[idx]                   = *(const uint16_t*)&bh;
    g_Wp[FDIM * FDIM + idx]     = *(const uint16_t*)&bm;
    g_Wp[2 * FDIM * FDIM + idx] = *(const uint16_t*)&bl;
}

// ---------------------------------------------------------------------------
// Kernel 2: spikes fp32 (exactly 0/1) -> bf16 (0x3F80 / 0)
// ---------------------------------------------------------------------------
__global__ void cvtb_kernel(const float* __restrict__ s) {
    size_t k = (size_t)blockIdx.x * 256 + threadIdx.x;   // 8 floats per thread
    const float4* p = (const float4*)s + k * 2;
    float4 a = p[0], b = p[1];
    uint4 o;
    o.x = (a.x != 0.0f ? 0x3F80u : 0u) | (a.y != 0.0f ? 0x3F800000u : 0u);
    o.y = (a.z != 0.0f ? 0x3F80u : 0u) | (a.w != 0.0f ? 0x3F800000u : 0u);
    o.z = (b.x != 0.0f ? 0x3F80u : 0u) | (b.y != 0.0f ? 0x3F800000u : 0u);
    o.w = (b.z != 0.0f ? 0x3F80u : 0u) | (b.w != 0.0f ? 0x3F800000u : 0u);
    ((uint4*)g_Sb)[k] = o;
}

// ---------------------------------------------------------------------------
// Kernel 3: bf16 HMMA GEMM  xs[M,512] = sum_p S @ Wp^T   (fp32 accum)
// Pipeline ordering (fixed vs R6): a stage is only overwritten AFTER the
// chunk that reads it has been fully consumed and barrier'd.
// ---------------------------------------------------------------------------
__global__ void __launch_bounds__(256, 1)
gemm_kernel() {
    extern __shared__ char smem[];
    const uint32_t sb = smem_u32(smem);
    const int tid = threadIdx.x;
    const int l = tid & 31, wid = tid >> 5;
    const int wm = wid & 3, wn = wid >> 2;          // 4 m-warps x 2 n-warps
    const int n0 = blockIdx.x * NT;
    const size_t m0 = (size_t)blockIdx.y * MT;

    float acc[4][8][4];                              // [mt][nt][frag] = 128 regs
    #pragma unroll
    for (int mt = 0; mt < 4; mt++)
        #pragma unroll
        for (int nt = 0; nt < 8; nt++)
            #pragma unroll
            for (int j = 0; j < 4; j++) acc[mt][nt][j] = 0.0f;

    // ---- stage loader: A[256m x 64k] + 3 x B[128n x 64k], swizzled 128B rows
    auto stage_load = [&](int c, int stg) {
        const uint32_t base = sb + stg * STG;
        #pragma unroll
        for (int q = 0; q < 8; q++) {                // A: 2048 cp16
            int u = q * 256 + tid;
            int row = u >> 3, seg = u & 7;
            cp16(base + row * 128 + ((seg * 16) ^ ((row & 7) << 4)),
                 g_Sb + (m0 + row) * FDIM + c * KC + seg * 8);
        }
        #pragma unroll
        for (int q = 0; q < 12; q++) {               // B: 3072 cp16
            int u = q * 256 + tid;
            int pl = u >> 10, rem = u & 1023;
            int row = rem >> 3, seg = rem & 7;
            cp16(base + A_SZ + pl * (NT * 128) + row * 128
                      + ((seg * 16) ^ ((row & 7) << 4)),
                 g_Wp + (size_t)pl * (FDIM * FDIM)
                      + (size_t)(n0 + row) * FDIM + c * KC + seg * 8);
        }
        asm volatile("cp.async.commit_group;" ::: "memory");
    };

    stage_load(0, 0);
    stage_load(1, 1);

    // per-lane ldmatrix address components
    const int rA = wm * 64 + (l & 15);               // A row (per mt: +16*mt)
    const int cA = (l >> 4) * 16;                    // A k-half byte offset
    const int qB = l >> 3;
    const int rBl = ((qB >> 1) << 3) + (l & 7);      // B row within 16-pair
    const int cB = (qB & 1) * 16;

    #pragma unroll 1
    for (int c = 0; c < NCHUNK; c++) {
        // Ensure chunk c's group is complete (all but the newest pending one).
        if (c + 1 < NCHUNK) asm volatile("cp.async.wait_group 1;" ::: "memory");
        else                asm volatile("cp.async.wait_group 0;" ::: "memory");
        __syncthreads();

        const uint32_t base = sb + (c & 1) * STG;
        const uint32_t aswz = ((uint32_t)(rA & 7)) << 4;
        const uint32_t bswz = ((uint32_t)(rBl & 7)) << 4;

        #pragma unroll
        for (int ks = 0; ks < 4; ks++) {
            uint32_t a[4][4];
            #pragma unroll
            for (int mt = 0; mt < 4; mt++) {
                uint32_t ad = base + (rA + mt * 16) * 128
                            + (((uint32_t)(ks * 32 + cA)) ^ aswz);
                LDSM4(a[mt][0], a[mt][1], a[mt][2], a[mt][3], ad);
            }
            #pragma unroll
            for (int pl = 0; pl < 3; pl++) {
                #pragma unroll
                for (int p2 = 0; p2 < 4; p2++) {     // 2 n-tiles per ldmatrix
                    uint32_t bd = base + A_SZ + pl * (NT * 128)
                                + (wn * 64 + p2 * 16 + rBl) * 128
                                + (((uint32_t)(ks * 32 + cB)) ^ bswz);
                    uint32_t b0, b1, b2, b3;
                    LDSM4(b0, b1, b2, b3, bd);
                    #pragma unroll
                    for (int mt = 0; mt < 4; mt++) {
                        HMMA(acc[mt][2 * p2],     a[mt], b0, b1);
                        HMMA(acc[mt][2 * p2 + 1], a[mt], b2, b3);
                    }
                }
            }
        }

        // Stage c&1 fully consumed by every warp -> safe to refill.
        __syncthreads();
        if (c + 2 < NCHUNK) stage_load(c + 2, c & 1);
    }

    // ---- epilogue: direct coalesced float2 stores ----
    #pragma unroll
    for (int mt = 0; mt < 4; mt++)
        #pragma unroll
        for (int nt = 0; nt < 8; nt++) {
            const size_t row = m0 + wm * 64 + mt * 16 + (l >> 2);
            const int    col = n0 + wn * 64 + nt * 8 + (l & 3) * 2;
            *(float2*)(g_xs + row * FDIM + col) =
                make_float2(acc[mt][nt][0], acc[mt][nt][1]);
            *(float2*)(g_xs + (row + 8) * FDIM + col) =
                make_float2(acc[mt][nt][2], acc[mt][nt][3]);
        }
}

// ---------------------------------------------------------------------------
// Kernel 4: LIF scan. Thread = one neuron (b,f); xs[t][bf] coalesced.
// fp32-exact in reference op order.
// ---------------------------------------------------------------------------
__global__ void __launch_bounds__(256)
scan_kernel(float* __restrict__ out) {
    const int bf = blockIdx.x * 256 + threadIdx.x;
    const float* p = g_xs + bf;
    float v = 0.0f, i = 0.0f, z = 0.0f;

    for (int t = 0; t < T_STEPS; t += 8) {
        float x[8];
        #pragma unroll
        for (int u = 0; u < 8; u++)
            x[u] = p[(size_t)(t + u) * BF];
        #pragma unroll
        for (int u = 0; u < 8; u++) {
            float vd = __fadd_rn(v, __fmul_rn(0.1f, __fadd_rn(-v, i)));
            float id = __fadd_rn(i, -__fmul_rn(0.2f, i));
            bool s = vd > 1.0f;
            z = s ? 1.0f : 0.0f;
            v = s ? 0.0f : vd;
            i = __fadd_rn(id, x[u]);
        }
    }
    out[bf]          = z;
    out[BF + bf]     = v;
    out[2 * BF + bf] = i;
}

// ---------------------------------------------------------------------------
extern "C" void kernel_launch(void* const* d_in, const int* in_sizes, int n_in,
                              void* d_out, int out_size) {
    const float* spikes = (const float*)d_in[0];  // [T, B, F] fp32 (binary)
    const float* W      = (const float*)d_in[1];  // [F, F] fp32
    float* out          = (float*)d_out;          // [3, B, F] fp32
    (void)in_sizes; (void)n_in; (void)out_size;

    cudaFuncSetAttribute(gemm_kernel,
                         cudaFuncAttributeMaxDynamicSharedMemorySize, SMEM_TOTAL);

    wsplit_kernel<<<(FDIM * FDIM) / 256, 256>>>(W);
    cvtb_kernel<<<(int)((size_t)MROWS * FDIM / 8 / 256), 256>>>(spikes);
    gemm_kernel<<<dim3(FDIM / NT, MROWS / MT), 256, SMEM_TOTAL>>>();
    scan_kernel<<<BF / 256, 256>>>(out);
}

// round 8
// speedup vs baseline: 3.6939x; 1.3020x over previous
#include <cuda_runtime.h>
#include <cuda_fp16.h>
#include <cstdint>

// ---------------------------------------------------------------------------
#define T_STEPS 1024
#define BATCH   256
#define FDIM    512
#define MROWS   (T_STEPS * BATCH)      // 262144
#define BF      (BATCH * FDIM)         // 131072

// GEMM tiling: CTA 256m x 128n, KC=64, 2-stage cp.async, 8 warps (4m x 2n),
// warp tile 64m x 64n, 2 fp16 planes accumulated into one fp32 accumulator.
#define MT      256
#define NT      128
#define KC      64
#define NCHUNK  (FDIM / KC)            // 8
#define NPLANE  2
#define A_SZ    (MT * 128)             // 32768 B  (256 rows x 128 B)
#define B_SZ    (NPLANE * NT * 128)    // 32768 B  (2 planes x 128 rows x 128 B)
#define STG     (A_SZ + B_SZ)          // 65536 B
#define SMEM_TOTAL (2 * STG)           // 131072 B

// Device scratch (static arrays are the sanctioned scratch mechanism)
__device__ uint16_t g_Sh[(size_t)MROWS * FDIM];        // spikes fp16 (268 MB)
__device__ uint16_t g_Wp[NPLANE * FDIM * FDIM];        // fp16 planes hi/lo
__device__ float    g_xs[(size_t)MROWS * FDIM];        // fc outputs (512 MB)

// ---------------------------------------------------------------------------
__device__ __forceinline__ uint32_t smem_u32(const void* p) {
    uint32_t a;
    asm("{ .reg .u64 t; cvta.to.shared.u64 t, %1; cvt.u32.u64 %0, t; }"
        : "=r"(a) : "l"(p));
    return a;
}
__device__ __forceinline__ void cp16(uint32_t dst, const void* src) {
    asm volatile("cp.async.cg.shared.global [%0], [%1], 16;"
                 :: "r"(dst), "l"(src) : "memory");
}
#define LDSM4(r0, r1, r2, r3, addr)                                        \
    asm volatile("ldmatrix.sync.aligned.m8n8.x4.shared.b16 "               \
                 "{%0,%1,%2,%3}, [%4];"                                    \
                 : "=r"(r0), "=r"(r1), "=r"(r2), "=r"(r3) : "r"(addr))

#define HMMA(c, a, b0_, b1_)                                               \
    asm volatile("mma.sync.aligned.m16n8k16.row.col.f32.f16.f16.f32 "      \
                 "{%0,%1,%2,%3}, {%4,%5,%6,%7}, {%8,%9}, {%0,%1,%2,%3};"   \
                 : "+f"((c)[0]), "+f"((c)[1]), "+f"((c)[2]), "+f"((c)[3])  \
                 : "r"((a)[0]), "r"((a)[1]), "r"((a)[2]), "r"((a)[3]),     \
                   "r"(b0_), "r"(b1_))

// ---------------------------------------------------------------------------
// Kernel 1: exact 2-way fp16 split of W.
// w = wh + wl + r, |r| <= |w|*2^-24 + 2^-25 (subnormal-safe).
// ---------------------------------------------------------------------------
__global__ void wsplit_kernel(const float* __restrict__ W) {
    int idx = blockIdx.x * 256 + threadIdx.x;       // 262144 = 512*512
    float w = W[idx];
    __half wh = __float2half_rn(w);
    float r1 = w - __half2float(wh);                // exact in fp32
    __half wl = __float2half_rn(r1);
    g_Wp[idx]               = *(const uint16_t*)&wh;
    g_Wp[FDIM * FDIM + idx] = *(const uint16_t*)&wl;
}

// ---------------------------------------------------------------------------
// Kernel 2: spikes fp32 (exactly 0/1) -> fp16 (0x3C00 / 0)
// ---------------------------------------------------------------------------
__global__ void cvth_kernel(const float* __restrict__ s) {
    size_t k = (size_t)blockIdx.x * 256 + threadIdx.x;   // 8 floats per thread
    const float4* p = (const float4*)s + k * 2;
    float4 a = p[0], b = p[1];
    uint4 o;
    o.x = (a.x != 0.0f ? 0x3C00u : 0u) | (a.y != 0.0f ? 0x3C000000u : 0u);
    o.y = (a.z != 0.0f ? 0x3C00u : 0u) | (a.w != 0.0f ? 0x3C000000u : 0u);
    o.z = (b.x != 0.0f ? 0x3C00u : 0u) | (b.y != 0.0f ? 0x3C000000u : 0u);
    o.w = (b.z != 0.0f ? 0x3C00u : 0u) | (b.w != 0.0f ? 0x3C000000u : 0u);
    ((uint4*)g_Sh)[k] = o;
}

// ---------------------------------------------------------------------------
// Kernel 3: fp16 HMMA GEMM  xs[M,512] = sum_p S @ Wp^T   (fp32 accum)
// Stage is only overwritten AFTER its chunk is fully consumed (verified R7).
// ---------------------------------------------------------------------------
__global__ void __launch_bounds__(256, 1)
gemm_kernel() {
    extern __shared__ char smem[];
    const uint32_t sb = smem_u32(smem);
    const int tid = threadIdx.x;
    const int l = tid & 31, wid = tid >> 5;
    const int wm = wid & 3, wn = wid >> 2;          // 4 m-warps x 2 n-warps
    const int n0 = blockIdx.x * NT;
    const size_t m0 = (size_t)blockIdx.y * MT;

    float acc[4][8][4];                              // [mt][nt][frag] = 128 regs
    #pragma unroll
    for (int mt = 0; mt < 4; mt++)
        #pragma unroll
        for (int nt = 0; nt < 8; nt++)
            #pragma unroll
            for (int j = 0; j < 4; j++) acc[mt][nt][j] = 0.0f;

    // ---- stage loader: A[256m x 64k] + 2 x B[128n x 64k], swizzled 128B rows
    auto stage_load = [&](int c, int stg) {
        const uint32_t base = sb + stg * STG;
        #pragma unroll
        for (int q = 0; q < 8; q++) {                // A: 2048 cp16
            int u = q * 256 + tid;
            int row = u >> 3, seg = u & 7;
            cp16(base + row * 128 + ((seg * 16) ^ ((row & 7) << 4)),
                 g_Sh + (m0 + row) * FDIM + c * KC + seg * 8);
        }
        #pragma unroll
        for (int q = 0; q < 8; q++) {                // B: 2048 cp16 (2 planes)
            int u = q * 256 + tid;
            int pl = u >> 10, rem = u & 1023;
            int row = rem >> 3, seg = rem & 7;
            cp16(base + A_SZ + pl * (NT * 128) + row * 128
                      + ((seg * 16) ^ ((row & 7) << 4)),
                 g_Wp + (size_t)pl * (FDIM * FDIM)
                      + (size_t)(n0 + row) * FDIM + c * KC + seg * 8);
        }
        asm volatile("cp.async.commit_group;" ::: "memory");
    };

    stage_load(0, 0);
    stage_load(1, 1);

    // per-lane ldmatrix address components
    const int rA = wm * 64 + (l & 15);               // A row (per mt: +16*mt)
    const int cA = (l >> 4) * 16;                    // A k-half byte offset
    const int qB = l >> 3;
    const int rBl = ((qB >> 1) << 3) + (l & 7);      // B row within 16-pair
    const int cB = (qB & 1) * 16;

    #pragma unroll 1
    for (int c = 0; c < NCHUNK; c++) {
        if (c + 1 < NCHUNK) asm volatile("cp.async.wait_group 1;" ::: "memory");
        else                asm volatile("cp.async.wait_group 0;" ::: "memory");
        __syncthreads();

        const uint32_t base = sb + (c & 1) * STG;
        const uint32_t aswz = ((uint32_t)(rA & 7)) << 4;
        const uint32_t bswz = ((uint32_t)(rBl & 7)) << 4;

        #pragma unroll
        for (int ks = 0; ks < 4; ks++) {
            uint32_t a[4][4];
            #pragma unroll
            for (int mt = 0; mt < 4; mt++) {
                uint32_t ad = base + (rA + mt * 16) * 128
                            + (((uint32_t)(ks * 32 + cA)) ^ aswz);
                LDSM4(a[mt][0], a[mt][1], a[mt][2], a[mt][3], ad);
            }
            #pragma unroll
            for (int pl = 0; pl < NPLANE; pl++) {
                #pragma unroll
                for (int p2 = 0; p2 < 4; p2++) {     // 2 n-tiles per ldmatrix
                    uint32_t bd = base + A_SZ + pl * (NT * 128)
                                + (wn * 64 + p2 * 16 + rBl) * 128
                                + (((uint32_t)(ks * 32 + cB)) ^ bswz);
                    uint32_t b0, b1, b2, b3;
                    LDSM4(b0, b1, b2, b3, bd);
                    #pragma unroll
                    for (int mt = 0; mt < 4; mt++) {
                        HMMA(acc[mt][2 * p2],     a[mt], b0, b1);
                        HMMA(acc[mt][2 * p2 + 1], a[mt], b2, b3);
                    }
                }
            }
        }

        __syncthreads();                 // stage (c&1) fully consumed
        if (c + 2 < NCHUNK) stage_load(c + 2, c & 1);
    }

    // ---- epilogue: direct coalesced float2 stores ----
    #pragma unroll
    for (int mt = 0; mt < 4; mt++)
        #pragma unroll
        for (int nt = 0; nt < 8; nt++) {
            const size_t row = m0 + wm * 64 + mt * 16 + (l >> 2);
            const int    col = n0 + wn * 64 + nt * 8 + (l & 3) * 2;
            *(float2*)(g_xs + row * FDIM + col) =
                make_float2(acc[mt][nt][0], acc[mt][nt][1]);
            *(float2*)(g_xs + (row + 8) * FDIM + col) =
                make_float2(acc[mt][nt][2], acc[mt][nt][3]);
        }
}

// ---------------------------------------------------------------------------
// Kernel 4: LIF scan. Thread = one neuron (b,f); xs[t][bf] coalesced.
// fp32-exact in reference op order; 16-deep load batch for MLP.
// ---------------------------------------------------------------------------
__global__ void __launch_bounds__(256)
scan_kernel(float* __restrict__ out) {
    const int bf = blockIdx.x * 256 + threadIdx.x;
    const float* p = g_xs + bf;
    float v = 0.0f, i = 0.0f, z = 0.0f;

    for (int t = 0; t < T_STEPS; t += 16) {
        float x[16];
        #pragma unroll
        for (int u = 0; u < 16; u++)
            x[u] = p[(size_t)(t + u) * BF];
        #pragma unroll
        for (int u = 0; u < 16; u++) {
            float vd = __fadd_rn(v, __fmul_rn(0.1f, __fadd_rn(-v, i)));
            float id = __fadd_rn(i, -__fmul_rn(0.2f, i));
            bool s = vd > 1.0f;
            z = s ? 1.0f : 0.0f;
            v = s ? 0.0f : vd;
            i = __fadd_rn(id, x[u]);
        }
    }
    out[bf]          = z;
    out[BF + bf]     = v;
    out[2 * BF + bf] = i;
}

// ---------------------------------------------------------------------------
extern "C" void kernel_launch(void* const* d_in, const int* in_sizes, int n_in,
                              void* d_out, int out_size) {
    const float* spikes = (const float*)d_in[0];  // [T, B, F] fp32 (binary)
    const float* W      = (const float*)d_in[1];  // [F, F] fp32
    float* out          = (float*)d_out;          // [3, B, F] fp32
    (void)in_sizes; (void)n_in; (void)out_size;

    cudaFuncSetAttribute(gemm_kernel,
                         cudaFuncAttributeMaxDynamicSharedMemorySize, SMEM_TOTAL);

    wsplit_kernel<<<(FDIM * FDIM) / 256, 256>>>(W);
    cvth_kernel<<<(int)((size_t)MROWS * FDIM / 8 / 256), 256>>>(spikes);
    gemm_kernel<<<dim3(FDIM / NT, MROWS / MT), 256, SMEM_TOTAL>>>();
    scan_kernel<<<BF / 256, 256>>>(out);
}

// round 9
// speedup vs baseline: 3.7299x; 1.0097x over previous
#include <cuda_runtime.h>
#include <cuda_fp16.h>
#include <cstdint>

// ---------------------------------------------------------------------------
#define T_STEPS 1024
#define BATCH   256
#define FDIM    512
#define MROWS   (T_STEPS * BATCH)      // 262144
#define BF      (BATCH * FDIM)         // 131072

// GEMM tiling: CTA 256m x 128n, KC=64, 3-stage cp.async, 8 warps (4m x 2n),
// warp tile 64m x 64n, 2 fp16 planes accumulated into one fp32 accumulator.
#define MT      256
#define NT      128
#define KC      64
#define NCHUNK  (FDIM / KC)            // 8
#define NPLANE  2
#define NSTAGE  3
#define A_SZ    (MT * 128)             // 32768 B  (256 rows x 128 B)
#define B_SZ    (NPLANE * NT * 128)    // 32768 B  (2 planes x 128 rows x 128 B)
#define STG     (A_SZ + B_SZ)          // 65536 B
#define SMEM_TOTAL (NSTAGE * STG)      // 196608 B

// Device scratch (static arrays are the sanctioned scratch mechanism)
__device__ uint16_t g_Sh[(size_t)MROWS * FDIM];        // spikes fp16 (268 MB)
__device__ uint16_t g_Wp[NPLANE * FDIM * FDIM];        // fp16 planes hi/lo
__device__ float    g_xs[(size_t)MROWS * FDIM];        // fc outputs (512 MB)

// ---------------------------------------------------------------------------
__device__ __forceinline__ uint32_t smem_u32(const void* p) {
    uint32_t a;
    asm("{ .reg .u64 t; cvta.to.shared.u64 t, %1; cvt.u32.u64 %0, t; }"
        : "=r"(a) : "l"(p));
    return a;
}
__device__ __forceinline__ void cp16(uint32_t dst, const void* src) {
    asm volatile("cp.async.cg.shared.global [%0], [%1], 16;"
                 :: "r"(dst), "l"(src) : "memory");
}
#define LDSM4(r0, r1, r2, r3, addr)                                        \
    asm volatile("ldmatrix.sync.aligned.m8n8.x4.shared.b16 "               \
                 "{%0,%1,%2,%3}, [%4];"                                    \
                 : "=r"(r0), "=r"(r1), "=r"(r2), "=r"(r3) : "r"(addr))

#define HMMA(c, a, b0_, b1_)                                               \
    asm volatile("mma.sync.aligned.m16n8k16.row.col.f32.f16.f16.f32 "      \
                 "{%0,%1,%2,%3}, {%4,%5,%6,%7}, {%8,%9}, {%0,%1,%2,%3};"   \
                 : "+f"((c)[0]), "+f"((c)[1]), "+f"((c)[2]), "+f"((c)[3])  \
                 : "r"((a)[0]), "r"((a)[1]), "r"((a)[2]), "r"((a)[3]),     \
                   "r"(b0_), "r"(b1_))

// ---------------------------------------------------------------------------
// Kernel 1: exact 2-way fp16 split of W.
// w = wh + wl + r, |r| <= |w|*2^-24 + 2^-25 (subnormal-safe).
// ---------------------------------------------------------------------------
__global__ void wsplit_kernel(const float* __restrict__ W) {
    int idx = blockIdx.x * 256 + threadIdx.x;       // 262144 = 512*512
    float w = W[idx];
    __half wh = __float2half_rn(w);
    float r1 = w - __half2float(wh);                // exact in fp32
    __half wl = __float2half_rn(r1);
    g_Wp[idx]               = *(const uint16_t*)&wh;
    g_Wp[FDIM * FDIM + idx] = *(const uint16_t*)&wl;
}

// ---------------------------------------------------------------------------
// Kernel 2: spikes fp32 (exactly 0/1) -> fp16 (0x3C00 / 0)
// ---------------------------------------------------------------------------
__global__ void cvth_kernel(const float* __restrict__ s) {
    size_t k = (size_t)blockIdx.x * 256 + threadIdx.x;   // 8 floats per thread
    const float4* p = (const float4*)s + k * 2;
    float4 a = p[0], b = p[1];
    uint4 o;
    o.x = (a.x != 0.0f ? 0x3C00u : 0u) | (a.y != 0.0f ? 0x3C000000u : 0u);
    o.y = (a.z != 0.0f ? 0x3C00u : 0u) | (a.w != 0.0f ? 0x3C000000u : 0u);
    o.z = (b.x != 0.0f ? 0x3C00u : 0u) | (b.y != 0.0f ? 0x3C000000u : 0u);
    o.w = (b.z != 0.0f ? 0x3C00u : 0u) | (b.w != 0.0f ? 0x3C000000u : 0u);
    ((uint4*)g_Sh)[k] = o;
}

// ---------------------------------------------------------------------------
// Kernel 3: fp16 HMMA GEMM  xs[M,512] = sum_p S @ Wp^T   (fp32 accum)
// 3-stage pipeline, ONE barrier per chunk. Slot (c+2)%3 was consumed by
// chunk c-1; the top-of-iteration barrier proves every warp finished c-1,
// so issuing its refill right after the barrier (before compute) is safe
// and overlaps the cp.async issue with this chunk's MMAs.
// ---------------------------------------------------------------------------
__global__ void __launch_bounds__(256, 1)
gemm_kernel() {
    extern __shared__ char smem[];
    const uint32_t sb = smem_u32(smem);
    const int tid = threadIdx.x;
    const int l = tid & 31, wid = tid >> 5;
    const int wm = wid & 3, wn = wid >> 2;          // 4 m-warps x 2 n-warps
    const int n0 = blockIdx.x * NT;
    const size_t m0 = (size_t)blockIdx.y * MT;

    float acc[4][8][4];                              // [mt][nt][frag] = 128 regs
    #pragma unroll
    for (int mt = 0; mt < 4; mt++)
        #pragma unroll
        for (int nt = 0; nt < 8; nt++)
            #pragma unroll
            for (int j = 0; j < 4; j++) acc[mt][nt][j] = 0.0f;

    // ---- stage loader: A[256m x 64k] + 2 x B[128n x 64k], swizzled 128B rows
    auto stage_load = [&](int c, int stg) {
        const uint32_t base = sb + stg * STG;
        #pragma unroll
        for (int q = 0; q < 8; q++) {                // A: 2048 cp16
            int u = q * 256 + tid;
            int row = u >> 3, seg = u & 7;
            cp16(base + row * 128 + ((seg * 16) ^ ((row & 7) << 4)),
                 g_Sh + (m0 + row) * FDIM + c * KC + seg * 8);
        }
        #pragma unroll
        for (int q = 0; q < 8; q++) {                // B: 2048 cp16 (2 planes)
            int u = q * 256 + tid;
            int pl = u >> 10, rem = u & 1023;
            int row = rem >> 3, seg = rem & 7;
            cp16(base + A_SZ + pl * (NT * 128) + row * 128
                      + ((seg * 16) ^ ((row & 7) << 4)),
                 g_Wp + (size_t)pl * (FDIM * FDIM)
                      + (size_t)(n0 + row) * FDIM + c * KC + seg * 8);
        }
        asm volatile("cp.async.commit_group;" ::: "memory");
    };

    stage_load(0, 0);
    stage_load(1, 1);

    // per-lane ldmatrix address components
    const int rA = wm * 64 + (l & 15);               // A row (per mt: +16*mt)
    const int cA = (l >> 4) * 16;                    // A k-half byte offset
    const int qB = l >> 3;
    const int rBl = ((qB >> 1) << 3) + (l & 7);      // B row within 16-pair
    const int cB = (qB & 1) * 16;

    #pragma unroll 1
    for (int c = 0; c < NCHUNK; c++) {
        // Groups in flight here: {c, c+1} (c+2 not yet issued).
        if (c + 1 < NCHUNK) asm volatile("cp.async.wait_group 1;" ::: "memory");
        else                asm volatile("cp.async.wait_group 0;" ::: "memory");
        __syncthreads();                 // all warps done with chunk c-1

        if (c + 2 < NCHUNK)              // refill slot (c+2)%3 == (c-1)%3
            stage_load(c + 2, (c + 2) % NSTAGE);

        const uint32_t base = sb + (c % NSTAGE) * STG;
        const uint32_t aswz = ((uint32_t)(rA & 7)) << 4;
        const uint32_t bswz = ((uint32_t)(rBl & 7)) << 4;

        #pragma unroll
        for (int ks = 0; ks < 4; ks++) {
            uint32_t a[4][4];
            #pragma unroll
            for (int mt = 0; mt < 4; mt++) {
                uint32_t ad = base + (rA + mt * 16) * 128
                            + (((uint32_t)(ks * 32 + cA)) ^ aswz);
                LDSM4(a[mt][0], a[mt][1], a[mt][2], a[mt][3], ad);
            }
            #pragma unroll
            for (int pl = 0; pl < NPLANE; pl++) {
                #pragma unroll
                for (int p2 = 0; p2 < 4; p2++) {     // 2 n-tiles per ldmatrix
                    uint32_t bd = base + A_SZ + pl * (NT * 128)
                                + (wn * 64 + p2 * 16 + rBl) * 128
                                + (((uint32_t)(ks * 32 + cB)) ^ bswz);
                    uint32_t b0, b1, b2, b3;
                    LDSM4(b0, b1, b2, b3, bd);
                    #pragma unroll
                    for (int mt = 0; mt < 4; mt++) {
                        HMMA(acc[mt][2 * p2],     a[mt], b0, b1);
                        HMMA(acc[mt][2 * p2 + 1], a[mt], b2, b3);
                    }
                }
            }
        }
    }

    // ---- epilogue: direct coalesced float2 stores ----
    #pragma unroll
    for (int mt = 0; mt < 4; mt++)
        #pragma unroll
        for (int nt = 0; nt < 8; nt++) {
            const size_t row = m0 + wm * 64 + mt * 16 + (l >> 2);
            const int    col = n0 + wn * 64 + nt * 8 + (l & 3) * 2;
            *(float2*)(g_xs + row * FDIM + col) =
                make_float2(acc[mt][nt][0], acc[mt][nt][1]);
            *(float2*)(g_xs + (row + 8) * FDIM + col) =
                make_float2(acc[mt][nt][2], acc[mt][nt][3]);
        }
}

// ---------------------------------------------------------------------------
// Kernel 4: LIF scan. Thread = one neuron (b,f); xs[t][bf] coalesced.
// fp32-exact in reference op order; 16-deep load batch for MLP.
// ---------------------------------------------------------------------------
__global__ void __launch_bounds__(256)
scan_kernel(float* __restrict__ out) {
    const int bf = blockIdx.x * 256 + threadIdx.x;
    const float* p = g_xs + bf;
    float v = 0.0f, i = 0.0f, z = 0.0f;

    for (int t = 0; t < T_STEPS; t += 16) {
        float x[16];
        #pragma unroll
        for (int u = 0; u < 16; u++)
            x[u] = p[(size_t)(t + u) * BF];
        #pragma unroll
        for (int u = 0; u < 16; u++) {
            float vd = __fadd_rn(v, __fmul_rn(0.1f, __fadd_rn(-v, i)));
            float id = __fadd_rn(i, -__fmul_rn(0.2f, i));
            bool s = vd > 1.0f;
            z = s ? 1.0f : 0.0f;
            v = s ? 0.0f : vd;
            i = __fadd_rn(id, x[u]);
        }
    }
    out[bf]          = z;
    out[BF + bf]     = v;
    out[2 * BF + bf] = i;
}

// ---------------------------------------------------------------------------
extern "C" void kernel_launch(void* const* d_in, const int* in_sizes, int n_in,
                              void* d_out, int out_size) {
    const float* spikes = (const float*)d_in[0];  // [T, B, F] fp32 (binary)
    const float* W      = (const float*)d_in[1];  // [F, F] fp32
    float* out          = (float*)d_out;          // [3, B, F] fp32
    (void)in_sizes; (void)n_in; (void)out_size;

    cudaFuncSetAttribute(gemm_kernel,
                         cudaFuncAttributeMaxDynamicSharedMemorySize, SMEM_TOTAL);

    wsplit_kernel<<<(FDIM * FDIM) / 256, 256>>>(W);
    cvth_kernel<<<(int)((size_t)MROWS * FDIM / 8 / 256), 256>>>(spikes);
    gemm_kernel<<<dim3(FDIM / NT, MROWS / MT), 256, SMEM_TOTAL>>>();
    scan_kernel<<<BF / 256, 256>>>(out);
}

// round 10
// speedup vs baseline: 3.8263x; 1.0258x over previous
#include <cuda_runtime.h>
#include <cuda_fp16.h>
#include <cstdint>

// ---------------------------------------------------------------------------
#define T_STEPS 1024
#define BATCH   256
#define FDIM    512
#define MROWS   (T_STEPS * BATCH)      // 262144
#define BF      (BATCH * FDIM)         // 131072

// GEMM tiling: CTA 128m x 128n, KC=64, 2-stage cp.async, 8 warps (4m x 2n),
// warp tile 32m x 64n, 2 fp16 planes into one fp32 accumulator.
// 96 KB smem/CTA -> 2 CTAs/SM: co-resident CTA hides chunk-boundary bubbles.
#define MT      128
#define NT      128
#define KC      64
#define NCHUNK  (FDIM / KC)            // 8
#define NPLANE  2
#define A_SZ    (MT * 128)             // 16384 B
#define B_SZ    (NPLANE * NT * 128)    // 32768 B
#define STG     (A_SZ + B_SZ)          // 49152 B
#define SMEM_TOTAL (2 * STG)           // 98304 B

// Device scratch (static arrays are the sanctioned scratch mechanism)
__device__ uint16_t g_Sh[(size_t)MROWS * FDIM];        // spikes fp16 (268 MB)
__device__ uint16_t g_Wp[NPLANE * FDIM * FDIM];        // fp16 planes hi/lo
__device__ float    g_xs[(size_t)MROWS * FDIM];        // fc outputs (512 MB)

// ---------------------------------------------------------------------------
__device__ __forceinline__ uint32_t smem_u32(const void* p) {
    uint32_t a;
    asm("{ .reg .u64 t; cvta.to.shared.u64 t, %1; cvt.u32.u64 %0, t; }"
        : "=r"(a) : "l"(p));
    return a;
}
__device__ __forceinline__ void cp16(uint32_t dst, const void* src) {
    asm volatile("cp.async.cg.shared.global [%0], [%1], 16;"
                 :: "r"(dst), "l"(src) : "memory");
}
#define LDSM4(r0, r1, r2, r3, addr)                                        \
    asm volatile("ldmatrix.sync.aligned.m8n8.x4.shared.b16 "               \
                 "{%0,%1,%2,%3}, [%4];"                                    \
                 : "=r"(r0), "=r"(r1), "=r"(r2), "=r"(r3) : "r"(addr))

#define HMMA(c, a, b0_, b1_)                                               \
    asm volatile("mma.sync.aligned.m16n8k16.row.col.f32.f16.f16.f32 "      \
                 "{%0,%1,%2,%3}, {%4,%5,%6,%7}, {%8,%9}, {%0,%1,%2,%3};"   \
                 : "+f"((c)[0]), "+f"((c)[1]), "+f"((c)[2]), "+f"((c)[3])  \
                 : "r"((a)[0]), "r"((a)[1]), "r"((a)[2]), "r"((a)[3]),     \
                   "r"(b0_), "r"(b1_))

// ---------------------------------------------------------------------------
// Kernel 1: exact 2-way fp16 split of W.
// w = wh + wl + r, |r| <= |w|*2^-24 + 2^-25 (subnormal-safe).
// ---------------------------------------------------------------------------
__global__ void wsplit_kernel(const float* __restrict__ W) {
    int idx = blockIdx.x * 256 + threadIdx.x;       // 262144 = 512*512
    float w = W[idx];
    __half wh = __float2half_rn(w);
    float r1 = w - __half2float(wh);                // exact in fp32
    __half wl = __float2half_rn(r1);
    g_Wp[idx]               = *(const uint16_t*)&wh;
    g_Wp[FDIM * FDIM + idx] = *(const uint16_t*)&wl;
}

// ---------------------------------------------------------------------------
// Kernel 2: spikes fp32 (exactly 0/1) -> fp16 (0x3C00 / 0)
// ---------------------------------------------------------------------------
__global__ void cvth_kernel(const float* __restrict__ s) {
    size_t k = (size_t)blockIdx.x * 256 + threadIdx.x;   // 8 floats per thread
    const float4* p = (const float4*)s + k * 2;
    float4 a = p[0], b = p[1];
    uint4 o;
    o.x = (a.x != 0.0f ? 0x3C00u : 0u) | (a.y != 0.0f ? 0x3C000000u : 0u);
    o.y = (a.z != 0.0f ? 0x3C00u : 0u) | (a.w != 0.0f ? 0x3C000000u : 0u);
    o.z = (b.x != 0.0f ? 0x3C00u : 0u) | (b.y != 0.0f ? 0x3C000000u : 0u);
    o.w = (b.z != 0.0f ? 0x3C00u : 0u) | (b.w != 0.0f ? 0x3C000000u : 0u);
    ((uint4*)g_Sh)[k] = o;
}

// ---------------------------------------------------------------------------
// Kernel 3: fp16 HMMA GEMM  xs[M,512] = sum_p S @ Wp^T   (fp32 accum)
// 2 stages; stage refilled only AFTER its chunk is fully consumed (R8-safe
// ordering). The exposed refill window is hidden by the co-resident CTA.
// ---------------------------------------------------------------------------
__global__ void __launch_bounds__(256, 2)
gemm_kernel() {
    extern __shared__ char smem[];
    const uint32_t sb = smem_u32(smem);
    const int tid = threadIdx.x;
    const int l = tid & 31, wid = tid >> 5;
    const int wm = wid & 3, wn = wid >> 2;          // 4 m-warps x 2 n-warps
    const int n0 = blockIdx.x * NT;
    const size_t m0 = (size_t)blockIdx.y * MT;

    float acc[2][8][4];                              // [mt][nt][frag] = 64 regs
    #pragma unroll
    for (int mt = 0; mt < 2; mt++)
        #pragma unroll
        for (int nt = 0; nt < 8; nt++)
            #pragma unroll
            for (int j = 0; j < 4; j++) acc[mt][nt][j] = 0.0f;

    // ---- stage loader: A[128m x 64k] + 2 x B[128n x 64k], swizzled 128B rows
    auto stage_load = [&](int c, int stg) {
        const uint32_t base = sb + stg * STG;
        #pragma unroll
        for (int q = 0; q < 4; q++) {                // A: 1024 cp16
            int u = q * 256 + tid;
            int row = u >> 3, seg = u & 7;
            cp16(base + row * 128 + ((seg * 16) ^ ((row & 7) << 4)),
                 g_Sh + (m0 + row) * FDIM + c * KC + seg * 8);
        }
        #pragma unroll
        for (int q = 0; q < 8; q++) {                // B: 2048 cp16 (2 planes)
            int u = q * 256 + tid;
            int pl = u >> 10, rem = u & 1023;
            int row = rem >> 3, seg = rem & 7;
            cp16(base + A_SZ + pl * (NT * 128) + row * 128
                      + ((seg * 16) ^ ((row & 7) << 4)),
                 g_Wp + (size_t)pl * (FDIM * FDIM)
                      + (size_t)(n0 + row) * FDIM + c * KC + seg * 8);
        }
        asm volatile("cp.async.commit_group;" ::: "memory");
    };

    stage_load(0, 0);
    stage_load(1, 1);

    // per-lane ldmatrix address components
    const int rA = wm * 32 + (l & 15);               // A row (per mt: +16*mt)
    const int cA = (l >> 4) * 16;                    // A k-half byte offset
    const int qB = l >> 3;
    const int rBl = ((qB >> 1) << 3) + (l & 7);      // B row within 16-pair
    const int cB = (qB & 1) * 16;

    #pragma unroll 1
    for (int c = 0; c < NCHUNK; c++) {
        if (c + 1 < NCHUNK) asm volatile("cp.async.wait_group 1;" ::: "memory");
        else                asm volatile("cp.async.wait_group 0;" ::: "memory");
        __syncthreads();

        const uint32_t base = sb + (c & 1) * STG;
        const uint32_t aswz = ((uint32_t)(rA & 7)) << 4;
        const uint32_t bswz = ((uint32_t)(rBl & 7)) << 4;

        #pragma unroll
        for (int ks = 0; ks < 4; ks++) {
            uint32_t a[2][4];
            #pragma unroll
            for (int mt = 0; mt < 2; mt++) {
                uint32_t ad = base + (rA + mt * 16) * 128
                            + (((uint32_t)(ks * 32 + cA)) ^ aswz);
                LDSM4(a[mt][0], a[mt][1], a[mt][2], a[mt][3], ad);
            }
            #pragma unroll
            for (int pl = 0; pl < NPLANE; pl++) {
                #pragma unroll
                for (int p2 = 0; p2 < 4; p2++) {     // 2 n-tiles per ldmatrix
                    uint32_t bd = base + A_SZ + pl * (NT * 128)
                                + (wn * 64 + p2 * 16 + rBl) * 128
                                + (((uint32_t)(ks * 32 + cB)) ^ bswz);
                    uint32_t b0, b1, b2, b3;
                    LDSM4(b0, b1, b2, b3, bd);
                    #pragma unroll
                    for (int mt = 0; mt < 2; mt++) {
                        HMMA(acc[mt][2 * p2],     a[mt], b0, b1);
                        HMMA(acc[mt][2 * p2 + 1], a[mt], b2, b3);
                    }
                }
            }
        }

        __syncthreads();                 // stage (c&1) fully consumed
        if (c + 2 < NCHUNK) stage_load(c + 2, c & 1);
    }

    // ---- epilogue: direct coalesced float2 stores ----
    #pragma unroll
    for (int mt = 0; mt < 2; mt++)
        #pragma unroll
        for (int nt = 0; nt < 8; nt++) {
            const size_t row = m0 + wm * 32 + mt * 16 + (l >> 2);
            const int    col = n0 + wn * 64 + nt * 8 + (l & 3) * 2;
            *(float2*)(g_xs + row * FDIM + col) =
                make_float2(acc[mt][nt][0], acc[mt][nt][1]);
            *(float2*)(g_xs + (row + 8) * FDIM + col) =
                make_float2(acc[mt][nt][2], acc[mt][nt][3]);
        }
}

// ---------------------------------------------------------------------------
// Kernel 4: LIF scan. Thread = one neuron (b,f); xs[t][bf] coalesced.
// fp32-exact in reference op order; 16-deep load batch for MLP.
// ---------------------------------------------------------------------------
__global__ void __launch_bounds__(256)
scan_kernel(float* __restrict__ out) {
    const int bf = blockIdx.x * 256 + threadIdx.x;
    const float* p = g_xs + bf;
    float v = 0.0f, i = 0.0f, z = 0.0f;

    for (int t = 0; t < T_STEPS; t += 16) {
        float x[16];
        #pragma unroll
        for (int u = 0; u < 16; u++)
            x[u] = p[(size_t)(t + u) * BF];
        #pragma unroll
        for (int u = 0; u < 16; u++) {
            float vd = __fadd_rn(v, __fmul_rn(0.1f, __fadd_rn(-v, i)));
            float id = __fadd_rn(i, -__fmul_rn(0.2f, i));
            bool s = vd > 1.0f;
            z = s ? 1.0f : 0.0f;
            v = s ? 0.0f : vd;
            i = __fadd_rn(id, x[u]);
        }
    }
    out[bf]          = z;
    out[BF + bf]     = v;
    out[2 * BF + bf] = i;
}

// ---------------------------------------------------------------------------
extern "C" void kernel_launch(void* const* d_in, const int* in_sizes, int n_in,
                              void* d_out, int out_size) {
    const float* spikes = (const float*)d_in[0];  // [T, B, F] fp32 (binary)
    const float* W      = (const float*)d_in[1];  // [F, F] fp32
    float* out          = (float*)d_out;          // [3, B, F] fp32
    (void)in_sizes; (void)n_in; (void)out_size;

    cudaFuncSetAttribute(gemm_kernel,
                         cudaFuncAttributeMaxDynamicSharedMemorySize, SMEM_TOTAL);

    wsplit_kernel<<<(FDIM * FDIM) / 256, 256>>>(W);
    cvth_kernel<<<(int)((size_t)MROWS * FDIM / 8 / 256), 256>>>(spikes);
    gemm_kernel<<<dim3(FDIM / NT, MROWS / MT), 256, SMEM_TOTAL>>>();
    scan_kernel<<<BF / 256, 256>>>(out);
}

// round 11
// speedup vs baseline: 3.8354x; 1.0024x over previous
#include <cuda_runtime.h>
#include <cuda_fp16.h>
#include <cstdint>

// ---------------------------------------------------------------------------
#define T_STEPS 1024
#define BATCH   256
#define FDIM    512
#define MROWS   (T_STEPS * BATCH)      // 262144
#define BF      (BATCH * FDIM)         // 131072

// GEMM tiling: CTA 128m x 128n, KC=64, 8 warps (4m x 2n), warp 32m x 64n.
// A = raw fp32 spikes, single-buffered, converted in-register to fp16.
// B = 2 fp16 planes, double-buffered with swizzle + ldmatrix (verified path).
#define MT      128
#define NT      128
#define KC      64
#define NCHUNK  (FDIM / KC)            // 8
#define NPLANE  2
#define A_STRIDE 288                   // fp32 row: 256 B data + 32 pad (banks)
#define AF32_SZ (MT * A_STRIDE)        // 36864 B
#define B_STG   (NPLANE * NT * 128)    // 32768 B
#define SMEM_TOTAL (AF32_SZ + 2 * B_STG)   // 102400 B -> 2 CTAs/SM

// Device scratch (static arrays are the sanctioned scratch mechanism)
__device__ uint16_t g_Wp[NPLANE * FDIM * FDIM];        // fp16 planes hi/lo
__device__ float    g_xs[(size_t)MROWS * FDIM];        // fc outputs (512 MB)

// ---------------------------------------------------------------------------
__device__ __forceinline__ uint32_t smem_u32(const void* p) {
    uint32_t a;
    asm("{ .reg .u64 t; cvta.to.shared.u64 t, %1; cvt.u32.u64 %0, t; }"
        : "=r"(a) : "l"(p));
    return a;
}
__device__ __forceinline__ void cp16(uint32_t dst, const void* src) {
    asm volatile("cp.async.cg.shared.global [%0], [%1], 16;"
                 :: "r"(dst), "l"(src) : "memory");
}
// Build one fp16x2 A-operand from two consecutive fp32 spikes in smem.
// PTX cvt.rn.f16x2.f32 d, a, b -> d = {hi=cvt(a), lo=cvt(b)}; conversion of
// exact 0.0/1.0 is exact.
__device__ __forceinline__ uint32_t lds_f32pair_to_h2(uint32_t addr) {
    float x, y; uint32_t r;
    asm volatile("ld.shared.v2.f32 {%0,%1}, [%2];" : "=f"(x), "=f"(y) : "r"(addr));
    asm("cvt.rn.f16x2.f32 %0, %1, %2;" : "=r"(r) : "f"(y), "f"(x));
    return r;
}
#define LDSM4(r0, r1, r2, r3, addr)                                        \
    asm volatile("ldmatrix.sync.aligned.m8n8.x4.shared.b16 "               \
                 "{%0,%1,%2,%3}, [%4];"                                    \
                 : "=r"(r0), "=r"(r1), "=r"(r2), "=r"(r3) : "r"(addr))

#define HMMA(c, a, b0_, b1_)                                               \
    asm volatile("mma.sync.aligned.m16n8k16.row.col.f32.f16.f16.f32 "      \
                 "{%0,%1,%2,%3}, {%4,%5,%6,%7}, {%8,%9}, {%0,%1,%2,%3};"   \
                 : "+f"((c)[0]), "+f"((c)[1]), "+f"((c)[2]), "+f"((c)[3])  \
                 : "r"((a)[0]), "r"((a)[1]), "r"((a)[2]), "r"((a)[3]),     \
                   "r"(b0_), "r"(b1_))

// ---------------------------------------------------------------------------
// Kernel 1: exact 2-way fp16 split of W.
// w = wh + wl + r, |r| <= |w|*2^-24 + 2^-25 (subnormal-safe).
// ---------------------------------------------------------------------------
__global__ void wsplit_kernel(const float* __restrict__ W) {
    int idx = blockIdx.x * 256 + threadIdx.x;       // 262144 = 512*512
    float w = W[idx];
    __half wh = __float2half_rn(w);
    float r1 = w - __half2float(wh);                // exact in fp32
    __half wl = __float2half_rn(r1);
    g_Wp[idx]               = *(const uint16_t*)&wh;
    g_Wp[FDIM * FDIM + idx] = *(const uint16_t*)&wl;
}

// ---------------------------------------------------------------------------
// Kernel 2: fp16 HMMA GEMM  xs[M,512] = sum_p S @ Wp^T   (fp32 accum)
// A read straight from the fp32 spike tensor (no pre-convert kernel).
// ---------------------------------------------------------------------------
__global__ void __launch_bounds__(256, 2)
gemm_kernel(const float* __restrict__ spk) {
    extern __shared__ char smem[];
    const uint32_t sb = smem_u32(smem);
    const int tid = threadIdx.x;
    const int l = tid & 31, wid = tid >> 5;
    const int wm = wid & 3, wn = wid >> 2;          // 4 m-warps x 2 n-warps
    const int n0 = blockIdx.x * NT;
    const size_t m0 = (size_t)blockIdx.y * MT;

    float acc[2][8][4];                              // [mt][nt][frag] = 64 regs
    #pragma unroll
    for (int mt = 0; mt < 2; mt++)
        #pragma unroll
        for (int nt = 0; nt < 8; nt++)
            #pragma unroll
            for (int j = 0; j < 4; j++) acc[mt][nt][j] = 0.0f;

    // ---- A loader: 128 rows x 256 B fp32, stride 288, no swizzle ----
    auto load_A = [&](int c) {
        #pragma unroll
        for (int q = 0; q < 8; q++) {                // 2048 cp16
            int u = q * 256 + tid;
            int row = u >> 4, seg = u & 15;
            cp16(sb + row * A_STRIDE + seg * 16,
                 spk + (m0 + row) * FDIM + c * KC + seg * 4);
        }
        asm volatile("cp.async.commit_group;" ::: "memory");
    };
    // ---- B loader: 2 planes x 128 rows x 128 B fp16, swizzled ----
    auto load_B = [&](int c, int stg) {
        const uint32_t base = sb + AF32_SZ + stg * B_STG;
        #pragma unroll
        for (int q = 0; q < 8; q++) {                // 2048 cp16
            int u = q * 256 + tid;
            int pl = u >> 10, rem = u & 1023;
            int row = rem >> 3, seg = rem & 7;
            cp16(base + pl * (NT * 128) + row * 128
                      + ((seg * 16) ^ ((row & 7) << 4)),
                 g_Wp + (size_t)pl * (FDIM * FDIM)
                      + (size_t)(n0 + row) * FDIM + c * KC + seg * 8);
        }
        asm volatile("cp.async.commit_group;" ::: "memory");
    };

    load_A(0);                      // group: A0  (commit inside)
    load_B(0, 0);                   // group: B0
    load_B(1, 1);                   // group: B1

    // per-lane address components
    const uint32_t aq = (uint32_t)((l >> 2) * A_STRIDE + (l & 3) * 8);
    const int qB = l >> 3;
    const int rBl = ((qB >> 1) << 3) + (l & 7);      // B row within 16-pair
    const int cB = (qB & 1) * 16;
    const uint32_t bswz = ((uint32_t)(rBl & 7)) << 4;

    #pragma unroll 1
    for (int c = 0; c < NCHUNK; c++) {
        // Need A(c) and B(c) complete. Newest pending group is B(c+1),
        // except at the last chunk where nothing newer exists.
        if (c < NCHUNK - 1) asm volatile("cp.async.wait_group 1;" ::: "memory");
        else                asm volatile("cp.async.wait_group 0;" ::: "memory");
        __syncthreads();

        const uint32_t abase = sb + (uint32_t)(wm * 32) * A_STRIDE + aq;
        const uint32_t bbase = sb + AF32_SZ + (c & 1) * B_STG;

        #pragma unroll
        for (int ks = 0; ks < 4; ks++) {
            uint32_t a[2][4];
            #pragma unroll
            for (int mt = 0; mt < 2; mt++) {
                uint32_t ad = abase + mt * 16 * A_STRIDE + ks * 64;
                a[mt][0] = lds_f32pair_to_h2(ad);                    // r, c
                a[mt][1] = lds_f32pair_to_h2(ad + 8 * A_STRIDE);     // r+8, c
                a[mt][2] = lds_f32pair_to_h2(ad + 32);               // r, c+8
                a[mt][3] = lds_f32pair_to_h2(ad + 8 * A_STRIDE + 32);// r+8, c+8
            }
            #pragma unroll
            for (int pl = 0; pl < NPLANE; pl++) {
                #pragma unroll
                for (int p2 = 0; p2 < 4; p2++) {     // 2 n-tiles per ldmatrix
                    uint32_t bd = bbase + pl * (NT * 128)
                                + (wn * 64 + p2 * 16 + rBl) * 128
                                + (((uint32_t)(ks * 32 + cB)) ^ bswz);
                    uint32_t b0, b1, b2, b3;
                    LDSM4(b0, b1, b2, b3, bd);
                    #pragma unroll
                    for (int mt = 0; mt < 2; mt++) {
                        HMMA(acc[mt][2 * p2],     a[mt], b0, b1);
                        HMMA(acc[mt][2 * p2 + 1], a[mt], b2, b3);
                    }
                }
            }
        }

        __syncthreads();                 // A buffer + B stage (c&1) consumed
        if (c + 1 < NCHUNK) load_A(c + 1);          // own commit group
        if (c + 2 < NCHUNK) load_B(c + 2, c & 1);   // own commit group
    }

    // ---- epilogue: direct coalesced float2 stores ----
    #pragma unroll
    for (int mt = 0; mt < 2; mt++)
        #pragma unroll
        for (int nt = 0; nt < 8; nt++) {
            const size_t row = m0 + wm * 32 + mt * 16 + (l >> 2);
            const int    col = n0 + wn * 64 + nt * 8 + (l & 3) * 2;
            *(float2*)(g_xs + row * FDIM + col) =
                make_float2(acc[mt][nt][0], acc[mt][nt][1]);
            *(float2*)(g_xs + (row + 8) * FDIM + col) =
                make_float2(acc[mt][nt][2], acc[mt][nt][3]);
        }
}

// ---------------------------------------------------------------------------
// Kernel 3: LIF scan. Thread = one neuron (b,f); xs[t][bf] coalesced.
// fp32-exact in reference op order; 16-deep load batch, streaming loads.
// ---------------------------------------------------------------------------
__global__ void __launch_bounds__(256)
scan_kernel(float* __restrict__ out) {
    const int bf = blockIdx.x * 256 + threadIdx.x;
    const float* p = g_xs + bf;
    float v = 0.0f, i = 0.0f, z = 0.0f;

    for (int t = 0; t < T_STEPS; t += 16) {
        float x[16];
        #pragma unroll
        for (int u = 0; u < 16; u++)
            x[u] = __ldcs(p + (size_t)(t + u) * BF);
        #pragma unroll
        for (int u = 0; u < 16; u++) {
            float vd = __fadd_rn(v, __fmul_rn(0.1f, __fadd_rn(-v, i)));
            float id = __fadd_rn(i, -__fmul_rn(0.2f, i));
            bool s = vd > 1.0f;
            z = s ? 1.0f : 0.0f;
            v = s ? 0.0f : vd;
            i = __fadd_rn(id, x[u]);
        }
    }
    out[bf]          = z;
    out[BF + bf]     = v;
    out[2 * BF + bf] = i;
}

// ---------------------------------------------------------------------------
extern "C" void kernel_launch(void* const* d_in, const int* in_sizes, int n_in,
                              void* d_out, int out_size) {
    const float* spikes = (const float*)d_in[0];  // [T, B, F] fp32 (binary)
    const float* W      = (const float*)d_in[1];  // [F, F] fp32
    float* out          = (float*)d_out;          // [3, B, F] fp32
    (void)in_sizes; (void)n_in; (void)out_size;

    cudaFuncSetAttribute(gemm_kernel,
                         cudaFuncAttributeMaxDynamicSharedMemorySize, SMEM_TOTAL);

    wsplit_kernel<<<(FDIM * FDIM) / 256, 256>>>(W);
    gemm_kernel<<<dim3(FDIM / NT, MROWS / MT), 256, SMEM_TOTAL>>>(spikes);
    scan_kernel<<<BF / 256, 256>>>(out);
}

// round 12
// speedup vs baseline: 3.8964x; 1.0159x over previous
#include <cuda_runtime.h>
#include <cuda_fp16.h>
#include <cstdint>

// ---------------------------------------------------------------------------
#define T_STEPS 1024
#define BATCH   256
#define FDIM    512
#define MROWS   (T_STEPS * BATCH)      // 262144
#define BF      (BATCH * FDIM)         // 131072

// GEMM tiling: CTA 128m x 128n, KC=64, 8 warps (4m x 2n), warp 32m x 64n.
// A = bit-packed spikes (1 bit/elem), whole 512-k strip in 10 KB smem,
//     expanded to fp16 in registers by ALU (hidden under HMMA).
// B = 2 fp16 planes, double-buffered, swizzle + ldmatrix (verified path).
#define MT      128
#define NT      128
#define KC      64
#define NCHUNK  (FDIM / KC)            // 8
#define NPLANE  2
#define ABIT_STRIDE 80                 // bytes per row: 64 B bits + 16 pad
#define ABIT_SZ (MT * ABIT_STRIDE)     // 10240 B
#define B_STG   (NPLANE * NT * 128)    // 32768 B
#define SMEM_TOTAL (ABIT_SZ + 2 * B_STG)   // 75776 B -> 2 CTAs/SM

// Device scratch (static arrays are the sanctioned scratch mechanism)
__device__ uint32_t g_Sbit[(size_t)MROWS * 16];        // 16 MB, 512 bits/row
__device__ uint16_t g_Wp[NPLANE * FDIM * FDIM];        // fp16 planes hi/lo
__device__ float    g_xs[(size_t)MROWS * FDIM];        // fc outputs (512 MB)

// ---------------------------------------------------------------------------
__device__ __forceinline__ uint32_t smem_u32(const void* p) {
    uint32_t a;
    asm("{ .reg .u64 t; cvta.to.shared.u64 t, %1; cvt.u32.u64 %0, t; }"
        : "=r"(a) : "l"(p));
    return a;
}
__device__ __forceinline__ void cp16(uint32_t dst, const void* src) {
    asm volatile("cp.async.cg.shared.global [%0], [%1], 16;"
                 :: "r"(dst), "l"(src) : "memory");
}
// 2-bit spike pair -> fp16x2 {lo=bit0, hi=bit1}, exact 0.0/1.0 halves.
__device__ __forceinline__ uint32_t expand2(uint32_t v2) {
    return (v2 & 1u) * 0x3C00u | (v2 & 2u) * 0x1E000000u;
}
#define LDSM4(r0, r1, r2, r3, addr)                                        \
    asm volatile("ldmatrix.sync.aligned.m8n8.x4.shared.b16 "               \
                 "{%0,%1,%2,%3}, [%4];"                                    \
                 : "=r"(r0), "=r"(r1), "=r"(r2), "=r"(r3) : "r"(addr))

#define HMMA(c, a, b0_, b1_)                                               \
    asm volatile("mma.sync.aligned.m16n8k16.row.col.f32.f16.f16.f32 "      \
                 "{%0,%1,%2,%3}, {%4,%5,%6,%7}, {%8,%9}, {%0,%1,%2,%3};"   \
                 : "+f"((c)[0]), "+f"((c)[1]), "+f"((c)[2]), "+f"((c)[3])  \
                 : "r"((a)[0]), "r"((a)[1]), "r"((a)[2]), "r"((a)[3]),     \
                   "r"(b0_), "r"(b1_))

// ---------------------------------------------------------------------------
// Kernel 1: exact 2-way fp16 split of W.
// ---------------------------------------------------------------------------
__global__ void wsplit_kernel(const float* __restrict__ W) {
    int idx = blockIdx.x * 256 + threadIdx.x;       // 262144 = 512*512
    float w = W[idx];
    __half wh = __float2half_rn(w);
    float r1 = w - __half2float(wh);                // exact in fp32
    __half wl = __float2half_rn(r1);
    g_Wp[idx]               = *(const uint16_t*)&wh;
    g_Wp[FDIM * FDIM + idx] = *(const uint16_t*)&wl;
}

// ---------------------------------------------------------------------------
// Kernel 2: pack spikes to bits. One warp per row; word j bit k = col j*32+k.
// ---------------------------------------------------------------------------
__global__ void pack_kernel(const float* __restrict__ spk) {
    const int row = blockIdx.x * 8 + (threadIdx.x >> 5);
    const int lane = threadIdx.x & 31;
    const float* p = spk + (size_t)row * FDIM;
    uint32_t myword = 0;
    #pragma unroll
    for (int it = 0; it < 16; it++) {
        float x = p[it * 32 + lane];
        uint32_t b = __ballot_sync(0xFFFFFFFFu, x != 0.0f);
        if (lane == it) myword = b;
    }
    if (lane < 16) g_Sbit[(size_t)row * 16 + lane] = myword;
}

// ---------------------------------------------------------------------------
// Kernel 3: fp16 HMMA GEMM  xs[M,512] = sum_p S @ Wp^T   (fp32 accum)
// ---------------------------------------------------------------------------
__global__ void __launch_bounds__(256, 2)
gemm_kernel() {
    extern __shared__ char smem[];
    const uint32_t sb = smem_u32(smem);
    const int tid = threadIdx.x;
    const int l = tid & 31, wid = tid >> 5;
    const int wm = wid & 3, wn = wid >> 2;          // 4 m-warps x 2 n-warps
    const int n0 = blockIdx.x * NT;
    const size_t m0 = (size_t)blockIdx.y * MT;

    float acc[2][8][4];                              // [mt][nt][frag] = 64 regs
    #pragma unroll
    for (int mt = 0; mt < 2; mt++)
        #pragma unroll
        for (int nt = 0; nt < 8; nt++)
            #pragma unroll
            for (int j = 0; j < 4; j++) acc[mt][nt][j] = 0.0f;

    // ---- A bits: whole 128-row x 512-bit strip, one group ----
    {
        #pragma unroll
        for (int q = 0; q < 2; q++) {                // 512 cp16
            int u = q * 256 + tid;
            int row = u >> 2, seg = u & 3;
            cp16(sb + row * ABIT_STRIDE + seg * 16,
                 g_Sbit + (m0 + row) * 16 + seg * 4);
        }
        asm volatile("cp.async.commit_group;" ::: "memory");
    }
    // ---- B loader: 2 planes x 128 rows x 128 B fp16, swizzled ----
    auto load_B = [&](int c, int stg) {
        const uint32_t base = sb + ABIT_SZ + stg * B_STG;
        #pragma unroll
        for (int q = 0; q < 8; q++) {                // 2048 cp16
            int u = q * 256 + tid;
            int pl = u >> 10, rem = u & 1023;
            int row = rem >> 3, seg = rem & 7;
            cp16(base + pl * (NT * 128) + row * 128
                      + ((seg * 16) ^ ((row & 7) << 4)),
                 g_Wp + (size_t)pl * (FDIM * FDIM)
                      + (size_t)(n0 + row) * FDIM + c * KC + seg * 8);
        }
        asm volatile("cp.async.commit_group;" ::: "memory");
    };

    load_B(0, 0);
    load_B(1, 1);

    // per-lane address components
    const int lq = l >> 2;                            // lane quarter 0..7
    const int sh0 = 2 * (l & 3);                      // bit offset in 16-col blk
    const int qB = l >> 3;
    const int rBl = ((qB >> 1) << 3) + (l & 7);       // B row within 16-pair
    const int cB = (qB & 1) * 16;
    const uint32_t bswz = ((uint32_t)(rBl & 7)) << 4;
    // A-bit smem addresses for this lane's 4 rows: (mt, half) combos
    const uint32_t abit0 = sb + (uint32_t)((wm * 32 + lq) * ABIT_STRIDE);

    #pragma unroll 1
    for (int c = 0; c < NCHUNK; c++) {
        // Pending groups: B(c+1) newest (A long complete).
        if (c < NCHUNK - 1) asm volatile("cp.async.wait_group 1;" ::: "memory");
        else                asm volatile("cp.async.wait_group 0;" ::: "memory");
        __syncthreads();

        // Load this chunk's 64 bits for each of the lane's 4 rows.
        uint32_t w0[2][2], w1[2][2];                 // [mt][half] -> lo/hi word
        #pragma unroll
        for (int mt = 0; mt < 2; mt++)
            #pragma unroll
            for (int h = 0; h < 2; h++) {
                uint32_t ad = abit0 + (uint32_t)((mt * 16 + h * 8) * ABIT_STRIDE
                                                 + c * 8);
                asm volatile("ld.shared.v2.b32 {%0,%1}, [%2];"
                             : "=r"(w0[mt][h]), "=r"(w1[mt][h]) : "r"(ad));
            }

        const uint32_t bbase = sb + ABIT_SZ + (c & 1) * B_STG;

        #pragma unroll
        for (int ks = 0; ks < 4; ks++) {
            const int shift = (ks & 1) * 16 + sh0;
            uint32_t a[2][4];
            #pragma unroll
            for (int mt = 0; mt < 2; mt++) {
                uint32_t vlo0 = ((ks < 2 ? w0[mt][0] : w1[mt][0]) >> shift) & 0x303u;
                uint32_t vlo1 = ((ks < 2 ? w0[mt][1] : w1[mt][1]) >> shift) & 0x303u;
                a[mt][0] = expand2(vlo0 & 3u);        // row r,   cols c,c+1
                a[mt][1] = expand2(vlo1 & 3u);        // row r+8, cols c,c+1
                a[mt][2] = expand2((vlo0 >> 8) & 3u); // row r,   cols c+8,c+9
                a[mt][3] = expand2((vlo1 >> 8) & 3u); // row r+8, cols c+8,c+9
            }
            #pragma unroll
            for (int pl = 0; pl < NPLANE; pl++) {
                #pragma unroll
                for (int p2 = 0; p2 < 4; p2++) {     // 2 n-tiles per ldmatrix
                    uint32_t bd = bbase + pl * (NT * 128)
                                + (wn * 64 + p2 * 16 + rBl) * 128
                                + (((uint32_t)(ks * 32 + cB)) ^ bswz);
                    uint32_t b0, b1, b2, b3;
                    LDSM4(b0, b1, b2, b3, bd);
                    #pragma unroll
                    for (int mt = 0; mt < 2; mt++) {
                        HMMA(acc[mt][2 * p2],     a[mt], b0, b1);
                        HMMA(acc[mt][2 * p2 + 1], a[mt], b2, b3);
                    }
                }
            }
        }

        __syncthreads();                 // B stage (c&1) consumed
        if (c + 2 < NCHUNK) load_B(c + 2, c & 1);
    }

    // ---- epilogue: direct coalesced float2 stores ----
    #pragma unroll
    for (int mt = 0; mt < 2; mt++)
        #pragma unroll
        for (int nt = 0; nt < 8; nt++) {
            const size_t row = m0 + wm * 32 + mt * 16 + (l >> 2);
            const int    col = n0 + wn * 64 + nt * 8 + (l & 3) * 2;
            *(float2*)(g_xs + row * FDIM + col) =
                make_float2(acc[mt][nt][0], acc[mt][nt][1]);
            *(float2*)(g_xs + (row + 8) * FDIM + col) =
                make_float2(acc[mt][nt][2], acc[mt][nt][3]);
        }
}

// ---------------------------------------------------------------------------
// Kernel 4: LIF scan. Thread = one neuron (b,f); xs[t][bf] coalesced.
// fp32-exact in reference op order; 16-deep load batch, streaming loads.
// ---------------------------------------------------------------------------
__global__ void __launch_bounds__(256)
scan_kernel(float* __restrict__ out) {
    const int bf = blockIdx.x * 256 + threadIdx.x;
    const float* p = g_xs + bf;
    float v = 0.0f, i = 0.0f, z = 0.0f;

    for (int t = 0; t < T_STEPS; t += 16) {
        float x[16];
        #pragma unroll
        for (int u = 0; u < 16; u++)
            x[u] = __ldcs(p + (size_t)(t + u) * BF);
        #pragma unroll
        for (int u = 0; u < 16; u++) {
            float vd = __fadd_rn(v, __fmul_rn(0.1f, __fadd_rn(-v, i)));
            float id = __fadd_rn(i, -__fmul_rn(0.2f, i));
            bool s = vd > 1.0f;
            z = s ? 1.0f : 0.0f;
            v = s ? 0.0f : vd;
            i = __fadd_rn(id, x[u]);
        }
    }
    out[bf]          = z;
    out[BF + bf]     = v;
    out[2 * BF + bf] = i;
}

// ---------------------------------------------------------------------------
extern "C" void kernel_launch(void* const* d_in, const int* in_sizes, int n_in,
                              void* d_out, int out_size) {
    const float* spikes = (const float*)d_in[0];  // [T, B, F] fp32 (binary)
    const float* W      = (const float*)d_in[1];  // [F, F] fp32
    float* out          = (float*)d_out;          // [3, B, F] fp32
    (void)in_sizes; (void)n_in; (void)out_size;

    cudaFuncSetAttribute(gemm_kernel,
                         cudaFuncAttributeMaxDynamicSharedMemorySize, SMEM_TOTAL);

    wsplit_kernel<<<(FDIM * FDIM) / 256, 256>>>(W);
    pack_kernel<<<MROWS / 8, 256>>>(spikes);
    gemm_kernel<<<dim3(FDIM / NT, MROWS / MT), 256, SMEM_TOTAL>>>();
    scan_kernel<<<BF / 256, 256>>>(out);
}